// round 16
// baseline (speedup 1.0000x reference)
#include <cuda_runtime.h>
#include <cuda_fp16.h>
#include <cstdint>

// Conv2d 3x3 VALID, C_in=C_out=8, 2048x2048 fp32 -> (8, 2046, 2046)
// Round 16: R12 structure (pure-fp16 mma, kx folded into K, RPW=2,
// double-buffered fragments, direct STG) + float4 staging loads
// (half the LDG count, higher MLP). Edge tile falls back to float2.

#define CIN   8
#define IH    2048
#define IW    2048
#define OHH   2046
#define OWW   2046
#define CH    (IH*IW)
#define TPX   128
#define NW    4
#define RPW   2
#define TR    (NW*RPW)      // 8 output rows per block
#define INR   (TR+2)        // 10 staged input rows
#define INPX  (TPX+2)       // 130
#define WPP   4             // u32 words per staged pixel
#define ROWSTRIDE (INPX*WPP)
#define NTHREADS  (NW*32)
#define NCHUNK (TPX/16)     // 8
#define IPR4   33           // items/row in float4 mode (32 quads + 1 pair)
#define NITEM4 (INR*IPR4)   // 330
#define NITEM2 (INR*(INPX/2)) // 650

typedef uint32_t u32;

__device__ __forceinline__ u32 f16x2_pack(float hv, float lv) {
    u32 r;
    asm("cvt.rn.f16x2.f32 %0, %1, %2;" : "=r"(r) : "f"(hv), "f"(lv));
    return r;
}

__device__ __forceinline__ void mma16(float* d,
                                      u32 a0, u32 a1, u32 a2, u32 a3,
                                      u32 b0, u32 b1) {
    asm volatile(
        "mma.sync.aligned.m16n8k16.row.col.f32.f16.f16.f32 "
        "{%0,%1,%2,%3}, {%4,%5,%6,%7}, {%8,%9}, {%0,%1,%2,%3};"
        : "+f"(d[0]), "+f"(d[1]), "+f"(d[2]), "+f"(d[3])
        : "r"(a0), "r"(a1), "r"(a2), "r"(a3), "r"(b0), "r"(b1));
}

__device__ __forceinline__ void mma8(float* d, u32 a0, u32 a1, u32 b0) {
    asm volatile(
        "mma.sync.aligned.m16n8k8.row.col.f32.f16.f16.f32 "
        "{%0,%1,%2,%3}, {%4,%5}, {%6}, {%0,%1,%2,%3};"
        : "+f"(d[0]), "+f"(d[1]), "+f"(d[2]), "+f"(d[3])
        : "r"(a0), "r"(a1), "r"(b0));
}

__global__ __launch_bounds__(NTHREADS)
void conv3x3_mma_kernel(const float* __restrict__ x,
                        const float* __restrict__ w,
                        float* __restrict__ out) {
    // stage[row][pixel][q]: word q = f16x2(cin 2q (low), cin 2q+1 (high))
    __shared__ u32 stage[INR * ROWSTRIDE];

    const int tid  = threadIdx.x;
    const int wid  = tid >> 5;
    const int lane = tid & 31;
    const int gid  = lane >> 2;   // 0..7 : M row (pixel) selector
    const int q    = lane & 3;    // 0..3 : k-pair / cout-pair selector

    int x0 = blockIdx.x * TPX; if (x0 > OWW - TPX) x0 = OWW - TPX;
    int y0 = blockIdx.y * TR;  if (y0 > OHH - TR)  y0 = OHH - TR;

    // ---- weight regs: wb[t] = f16x2(w[gid][2q+1][t] hi, w[gid][2q][t] lo) ----
    u32 wb[9];
    #pragma unroll
    for (int t = 0; t < 9; ++t) {
        int ky = t / 3, kx = t % 3;
        float w0v = __ldg(&w[((gid * CIN + 2 * q)     * 3 + ky) * 3 + kx]);
        float w1v = __ldg(&w[((gid * CIN + 2 * q + 1) * 3 + ky) * 3 + kx]);
        wb[t] = f16x2_pack(w1v, w0v);
    }

    // ---- stage inputs ----
    if ((x0 & 3) == 0) {
        // float4 path: 33 items/row (32 quads + one 2px pair)
        #pragma unroll
        for (int k = 0; k < (NITEM4 + NTHREADS - 1) / NTHREADS; ++k) {
            int it = tid + k * NTHREADS;
            if (it < NITEM4) {
                int b   = it / IPR4;
                int xit = it - b * IPR4;
                if (xit < 32) {
                    int xl = xit * 4;
                    const float* ip = x + (size_t)(y0 + b) * IW + (x0 + xl);
                    float4 v[8];
                    #pragma unroll
                    for (int c = 0; c < 8; ++c)
                        v[c] = *reinterpret_cast<const float4*>(ip + (size_t)c * CH);
                    u32 s[4][4];   // [pixel][q]
                    #pragma unroll
                    for (int j = 0; j < 4; ++j) {
                        s[0][j] = f16x2_pack(v[2*j+1].x, v[2*j].x);
                        s[1][j] = f16x2_pack(v[2*j+1].y, v[2*j].y);
                        s[2][j] = f16x2_pack(v[2*j+1].z, v[2*j].z);
                        s[3][j] = f16x2_pack(v[2*j+1].w, v[2*j].w);
                    }
                    u32* dst = &stage[(size_t)b * ROWSTRIDE + (size_t)xl * WPP];
                    #pragma unroll
                    for (int p = 0; p < 4; ++p)
                        reinterpret_cast<uint4*>(dst)[p] =
                            make_uint4(s[p][0], s[p][1], s[p][2], s[p][3]);
                } else {
                    int xl = 128;   // tail pair: px 128,129
                    const float* ip = x + (size_t)(y0 + b) * IW + (x0 + xl);
                    float2 v[8];
                    #pragma unroll
                    for (int c = 0; c < 8; ++c)
                        v[c] = *reinterpret_cast<const float2*>(ip + (size_t)c * CH);
                    u32 w0[4], w1[4];
                    #pragma unroll
                    for (int j = 0; j < 4; ++j) {
                        w0[j] = f16x2_pack(v[2*j+1].x, v[2*j].x);
                        w1[j] = f16x2_pack(v[2*j+1].y, v[2*j].y);
                    }
                    u32* dst = &stage[(size_t)b * ROWSTRIDE + (size_t)xl * WPP];
                    reinterpret_cast<uint4*>(dst)[0] = make_uint4(w0[0], w0[1], w0[2], w0[3]);
                    reinterpret_cast<uint4*>(dst)[1] = make_uint4(w1[0], w1[1], w1[2], w1[3]);
                }
            }
        }
    } else {
        // unaligned edge tile: float2 path (1/16 of CTAs)
        #pragma unroll
        for (int k = 0; k < (NITEM2 + NTHREADS - 1) / NTHREADS; ++k) {
            int it = tid + k * NTHREADS;
            if (it < NITEM2) {
                int b  = it / (INPX / 2);
                int xl = (it - b * (INPX / 2)) * 2;
                const float* ip = x + (size_t)(y0 + b) * IW + (x0 + xl);
                float2 v[8];
                #pragma unroll
                for (int c = 0; c < 8; ++c)
                    v[c] = *reinterpret_cast<const float2*>(ip + (size_t)c * CH);
                u32 w0[4], w1[4];
                #pragma unroll
                for (int j = 0; j < 4; ++j) {
                    w0[j] = f16x2_pack(v[2*j+1].x, v[2*j].x);
                    w1[j] = f16x2_pack(v[2*j+1].y, v[2*j].y);
                }
                u32* dst = &stage[(size_t)b * ROWSTRIDE + (size_t)xl * WPP];
                reinterpret_cast<uint4*>(dst)[0] = make_uint4(w0[0], w0[1], w0[2], w0[3]);
                reinterpret_cast<uint4*>(dst)[1] = make_uint4(w1[0], w1[1], w1[2], w1[3]);
            }
        }
    }
    __syncthreads();

    // ---- compute: warp handles output rows y0+2*wid, +1 ----
    const size_t PL = (size_t)OHH * OWW;
    const int r0 = y0 + RPW * wid;

    const u32* rbase[RPW + 2];
    #pragma unroll
    for (int ir = 0; ir < RPW + 2; ++ir)
        rbase[ir] = &stage[(size_t)(RPW * wid + ir) * ROWSTRIDE + (size_t)gid * WPP + q];

    // double-buffered fragments
    u32 L[2][4][3], H[2][4][3];
    #pragma unroll
    for (int ir = 0; ir < 4; ++ir) {
        const u32* rp = rbase[ir];
        #pragma unroll
        for (int kx = 0; kx < 3; ++kx) {
            L[0][ir][kx] = rp[kx * WPP];
            H[0][ir][kx] = rp[(kx + 8) * WPP];
        }
    }

    #pragma unroll
    for (int chunk = 0; chunk < NCHUNK; ++chunk) {
        const int cur = chunk & 1, nxt = cur ^ 1;

        if (chunk + 1 < NCHUNK) {
            const int co = (chunk + 1) * 16 * WPP;
            #pragma unroll
            for (int ir = 0; ir < 4; ++ir) {
                const u32* rp = rbase[ir] + co;
                #pragma unroll
                for (int kx = 0; kx < 3; ++kx) {
                    L[nxt][ir][kx] = rp[kx * WPP];
                    H[nxt][ir][kx] = rp[(kx + 8) * WPP];
                }
            }
        }

        float a0[4] = {0,0,0,0};
        float a1[4] = {0,0,0,0};
        #define Lc L[cur]
        #define Hc H[cur]
        mma16(a0, Lc[0][0],Hc[0][0], Lc[0][1],Hc[0][1], wb[0], wb[1]);
        mma16(a1, Lc[1][0],Hc[1][0], Lc[1][1],Hc[1][1], wb[0], wb[1]);
        mma16(a0, Lc[0][2],Hc[0][2], Lc[1][0],Hc[1][0], wb[2], wb[3]);
        mma16(a1, Lc[1][2],Hc[1][2], Lc[2][0],Hc[2][0], wb[2], wb[3]);
        mma16(a0, Lc[1][1],Hc[1][1], Lc[1][2],Hc[1][2], wb[4], wb[5]);
        mma16(a1, Lc[2][1],Hc[2][1], Lc[2][2],Hc[2][2], wb[4], wb[5]);
        mma16(a0, Lc[2][0],Hc[2][0], Lc[2][1],Hc[2][1], wb[6], wb[7]);
        mma16(a1, Lc[3][0],Hc[3][0], Lc[3][1],Hc[3][1], wb[6], wb[7]);
        mma8 (a0, Lc[2][2],Hc[2][2], wb[8]);
        mma8 (a1, Lc[3][2],Hc[3][2], wb[8]);
        #undef Lc
        #undef Hc

        // D: [0]=D[gid][2q] [1]=D[gid][2q+1] [2]=D[gid+8][2q] [3]=D[gid+8][2q+1]
        int pix = x0 + chunk * 16 + gid;
        float* op = out + (size_t)(2 * q) * PL + (size_t)r0 * OWW + pix;
        op[0]      = a0[0];  op[PL]     = a0[1];
        op[8]      = a0[2];  op[PL + 8] = a0[3];
        op += OWW;
        op[0]      = a1[0];  op[PL]     = a1[1];
        op[8]      = a1[2];  op[PL + 8] = a1[3];
    }
}

extern "C" void kernel_launch(void* const* d_in, const int* in_sizes, int n_in,
                              void* d_out, int out_size) {
    const float* x = (const float*)d_in[0];   // (8, 2048, 2048) fp32
    const float* w = (const float*)d_in[1];   // (8, 8, 3, 3) fp32
    float* out = (float*)d_out;               // (8, 2046, 2046) fp32

    dim3 grid((OWW + TPX - 1) / TPX,          // 16
              (OHH + TR - 1) / TR);           // 256
    conv3x3_mma_kernel<<<grid, NTHREADS>>>(x, w, out);
}

// round 17
// speedup vs baseline: 1.0332x; 1.0332x over previous
#include <cuda_runtime.h>
#include <cuda_fp16.h>
#include <cstdint>

// Conv2d 3x3 VALID, C_in=C_out=8, 2048x2048 fp32 -> (8, 2046, 2046)
// Round 17: R12 geometry/staging (pure-fp16, RPW=2, NW=4) with ldmatrix
// A-fragments: tap pairs (ky,0)+(ky,1) as K=16 (ldmatrix.x4) and (ky,2)
// as K=8 (ldmatrix.x2). 8 LDSM replace 24 LDS.32 per chunk; A fragments
// shared across the warp's two output rows.

#define CIN   8
#define IH    2048
#define IW    2048
#define OHH   2046
#define OWW   2046
#define CH    (IH*IW)
#define TPX   128
#define NW    4
#define RPW   2
#define TR    (NW*RPW)      // 8 output rows per block
#define INR   (TR+2)        // 10 staged input rows
#define INPX  (TPX+2)       // 130
#define WPP   4             // u32 words per staged pixel (16B)
#define ROWSTRIDE (INPX*WPP)
#define NTHREADS  (NW*32)
#define NCHUNK (TPX/16)     // 8
#define NITEM  (INR*(INPX/2))   // 650

typedef uint32_t u32;

__device__ __forceinline__ u32 f16x2_pack(float hv, float lv) {
    u32 r;
    asm("cvt.rn.f16x2.f32 %0, %1, %2;" : "=r"(r) : "f"(hv), "f"(lv));
    return r;
}

__device__ __forceinline__ u32 smem_u32(const void* p) {
    u32 a;
    asm("{ .reg .u64 t; cvta.to.shared.u64 t, %1; cvt.u32.u64 %0, t; }"
        : "=r"(a) : "l"(p));
    return a;
}

__device__ __forceinline__ void ldsm4(u32* r, u32 addr) {
    asm volatile("ldmatrix.sync.aligned.m8n8.x4.shared.b16 {%0,%1,%2,%3}, [%4];"
                 : "=r"(r[0]), "=r"(r[1]), "=r"(r[2]), "=r"(r[3]) : "r"(addr));
}

__device__ __forceinline__ void ldsm2(u32* r, u32 addr) {
    asm volatile("ldmatrix.sync.aligned.m8n8.x2.shared.b16 {%0,%1}, [%2];"
                 : "=r"(r[0]), "=r"(r[1]) : "r"(addr));
}

__device__ __forceinline__ void mma16(float* d, const u32* a, u32 b0, u32 b1) {
    asm volatile(
        "mma.sync.aligned.m16n8k16.row.col.f32.f16.f16.f32 "
        "{%0,%1,%2,%3}, {%4,%5,%6,%7}, {%8,%9}, {%0,%1,%2,%3};"
        : "+f"(d[0]), "+f"(d[1]), "+f"(d[2]), "+f"(d[3])
        : "r"(a[0]), "r"(a[1]), "r"(a[2]), "r"(a[3]), "r"(b0), "r"(b1));
}

__device__ __forceinline__ void mma8(float* d, const u32* a, u32 b0) {
    asm volatile(
        "mma.sync.aligned.m16n8k8.row.col.f32.f16.f16.f32 "
        "{%0,%1,%2,%3}, {%4,%5}, {%6}, {%0,%1,%2,%3};"
        : "+f"(d[0]), "+f"(d[1]), "+f"(d[2]), "+f"(d[3])
        : "r"(a[0]), "r"(a[1]), "r"(b0));
}

__global__ __launch_bounds__(NTHREADS)
void conv3x3_mma_kernel(const float* __restrict__ x,
                        const float* __restrict__ w,
                        float* __restrict__ out) {
    // stage[row][pixel][q]: word q = f16x2(cin 2q (low), cin 2q+1 (high))
    __shared__ u32 stage[INR * ROWSTRIDE];

    const int tid  = threadIdx.x;
    const int wid  = tid >> 5;
    const int lane = tid & 31;
    const int gid  = lane >> 2;   // 0..7 : M row (pixel) selector
    const int q    = lane & 3;    // 0..3 : k-pair / cout-pair selector

    int x0 = blockIdx.x * TPX; if (x0 > OWW - TPX) x0 = OWW - TPX;
    int y0 = blockIdx.y * TR;  if (y0 > OHH - TR)  y0 = OHH - TR;

    // ---- weight regs: wb[t] = f16x2(w[gid][2q+1][t] hi, w[gid][2q][t] lo)
    //      = B fragment (cout gid, cins 2q/2q+1) for tap t ----
    u32 wb[9];
    #pragma unroll
    for (int t = 0; t < 9; ++t) {
        int ky = t / 3, kx = t % 3;
        float w0v = __ldg(&w[((gid * CIN + 2 * q)     * 3 + ky) * 3 + kx]);
        float w1v = __ldg(&w[((gid * CIN + 2 * q + 1) * 3 + ky) * 3 + kx]);
        wb[t] = f16x2_pack(w1v, w0v);
    }

    // ---- stage inputs (R12 float2 path) ----
    #pragma unroll
    for (int k = 0; k < (NITEM + NTHREADS - 1) / NTHREADS; ++k) {
        int it = tid + k * NTHREADS;
        if (it < NITEM) {
            int b  = it / (INPX / 2);
            int xl = (it - b * (INPX / 2)) * 2;
            const float* ip = x + (size_t)(y0 + b) * IW + (x0 + xl);
            float2 v[8];
            #pragma unroll
            for (int c = 0; c < 8; ++c)
                v[c] = *reinterpret_cast<const float2*>(ip + (size_t)c * CH);
            u32 w0[4], w1[4];
            #pragma unroll
            for (int j = 0; j < 4; ++j) {
                w0[j] = f16x2_pack(v[2*j+1].x, v[2*j].x);
                w1[j] = f16x2_pack(v[2*j+1].y, v[2*j].y);
            }
            u32* dst = &stage[(size_t)b * ROWSTRIDE + (size_t)xl * WPP];
            reinterpret_cast<uint4*>(dst)[0] = make_uint4(w0[0], w0[1], w0[2], w0[3]);
            reinterpret_cast<uint4*>(dst)[1] = make_uint4(w1[0], w1[1], w1[2], w1[3]);
        }
    }
    __syncthreads();

    // ---- compute: warp handles output rows y0+2*wid, +1 ----
    const size_t PL = (size_t)OHH * OWW;
    const int r0 = y0 + RPW * wid;

    // ldmatrix per-thread row addresses (byte):
    //   x4: pixel offset t<16 ? t : t-15  (mats: rows0-7/8-15 @tap0, rows0-7/8-15 @tap1)
    //   x2: pixel offset (t&15) + 2       (tap kx=2)
    const u32 sbase = smem_u32(stage);
    const int p16 = (lane < 16) ? lane : lane - 15;
    const int p8  = (lane & 15) + 2;

    u32 adr16[RPW + 2], adr8[RPW + 2];
    #pragma unroll
    for (int s = 0; s < RPW + 2; ++s) {
        u32 rb = sbase + (u32)((RPW * wid + s) * ROWSTRIDE) * 4u;
        adr16[s] = rb + (u32)(p16 * WPP) * 4u;
        adr8[s]  = rb + (u32)(p8  * WPP) * 4u;
    }

    #pragma unroll
    for (int chunk = 0; chunk < NCHUNK; ++chunk) {
        // A fragments for 4 staged rows (shared by both output rows)
        u32 A16[RPW + 2][4], A8[RPW + 2][2];
        #pragma unroll
        for (int s = 0; s < RPW + 2; ++s) {
            ldsm4(A16[s], adr16[s]);
            ldsm2(A8[s],  adr8[s]);
            adr16[s] += 16 * WPP * 4;   // next chunk
            adr8[s]  += 16 * WPP * 4;
        }

        float a0[4] = {0,0,0,0};
        float a1[4] = {0,0,0,0};
        // interleave the two rows' chains
        mma16(a0, A16[0], wb[0], wb[1]);
        mma16(a1, A16[1], wb[0], wb[1]);
        mma16(a0, A16[1], wb[3], wb[4]);
        mma16(a1, A16[2], wb[3], wb[4]);
        mma16(a0, A16[2], wb[6], wb[7]);
        mma16(a1, A16[3], wb[6], wb[7]);
        mma8 (a0, A8[0], wb[2]);
        mma8 (a1, A8[1], wb[2]);
        mma8 (a0, A8[1], wb[5]);
        mma8 (a1, A8[2], wb[5]);
        mma8 (a0, A8[2], wb[8]);
        mma8 (a1, A8[3], wb[8]);

        // D: [0]=D[gid][2q] [1]=D[gid][2q+1] [2]=D[gid+8][2q] [3]=D[gid+8][2q+1]
        int pix = x0 + chunk * 16 + gid;
        float* op = out + (size_t)(2 * q) * PL + (size_t)r0 * OWW + pix;
        op[0]      = a0[0];  op[PL]     = a0[1];
        op[8]      = a0[2];  op[PL + 8] = a0[3];
        op += OWW;
        op[0]      = a1[0];  op[PL]     = a1[1];
        op[8]      = a1[2];  op[PL + 8] = a1[3];
    }
}

extern "C" void kernel_launch(void* const* d_in, const int* in_sizes, int n_in,
                              void* d_out, int out_size) {
    const float* x = (const float*)d_in[0];   // (8, 2048, 2048) fp32
    const float* w = (const float*)d_in[1];   // (8, 8, 3, 3) fp32
    float* out = (float*)d_out;               // (8, 2046, 2046) fp32

    dim3 grid((OWW + TPX - 1) / TPX,          // 16
              (OHH + TR - 1) / TR);           // 256
    conv3x3_mma_kernel<<<grid, NTHREADS>>>(x, w, out);
}